// round 7
// baseline (speedup 1.0000x reference)
#include <cuda_runtime.h>
#include <cuda_fp16.h>

// Fused LUT color-grade, GB300 (sm_103a), round 7.
// x: (4,3,1024,1024) f32, lut1d: (3,64) f32, lut3d: (17,17,17,3) f32.
//
// Dual-limited (L1 wavefronts + issue). This round: remove all F2I/I2F and
// clamp instructions via magic-number floor/frac (fma.rz into 2^23 mantissa)
// and fma.rn.sat for the 1D clip; interleave the 32B cell record.
//   cell (32B): base c000 (3 fp16) + scale (fp16) + 21 int8 corner deltas
//   res_ch = base_ch + (sum w_c * d_c) * scale/16384  via dp2a on s16 weights.

namespace {
constexpr int kHW      = 1024 * 1024;
constexpr int kBatch   = 4;
constexpr int kM       = 17;
constexpr int kCells   = 16 * 16 * 16;               // 4096
constexpr int kThreads = 1024;
constexpr int kSmemBytes = kCells * 32 + 3 * 64 * 4; // 131,840 B
}  // namespace

__device__ uint4   g_cells[2 * kCells];   // interleaved: cell c -> [2c], [2c+1]
__device__ __half2 g_pair1d[3 * 64];

static __device__ __forceinline__ unsigned packh2(float a, float b) {
    __half2 h = __halves2half2(__float2half(a), __float2half(b));
    return *reinterpret_cast<unsigned*>(&h);
}
static __device__ __forceinline__ unsigned pack4b(int b0, int b1, int b2, int b3) {
    return (unsigned)(b0 & 0xFF) | ((unsigned)(b1 & 0xFF) << 8) |
           ((unsigned)(b2 & 0xFF) << 16) | ((unsigned)(b3 & 0xFF) << 24);
}

extern "C" __global__ void lut_prep_kernel(const float* __restrict__ lut1d,
                                           const float* __restrict__ lut3d) {
    int t = blockIdx.x * blockDim.x + threadIdx.x;
    if (t < kCells) {
        int ir = t >> 8, ig = (t >> 4) & 15, ib = t & 15;
        float v[8][3];
#pragma unroll
        for (int c = 0; c < 8; ++c) {
            int dr = c >> 2, dg = (c >> 1) & 1, db = c & 1;
            const float* p =
                lut3d + (((ir + dr) * kM + (ig + dg)) * kM + (ib + db)) * 3;
            v[c][0] = p[0]; v[c][1] = p[1]; v[c][2] = p[2];
        }
        float d[8][3];
        float maxd = 0.0f;
#pragma unroll
        for (int c = 1; c < 8; ++c)
#pragma unroll
            for (int ch = 0; ch < 3; ++ch) {
                d[c][ch] = v[c][ch] - v[0][ch];
                maxd = fmaxf(maxd, fabsf(d[c][ch]));
            }
        float inv = (maxd > 0.0f) ? 127.0f / maxd : 0.0f;
        int q[8][3];
#pragma unroll
        for (int c = 1; c < 8; ++c)
#pragma unroll
            for (int ch = 0; ch < 3; ++ch) {
                int qq = __float2int_rn(d[c][ch] * inv);
                q[c][ch] = max(-127, min(127, qq));
            }
        float scale = maxd * (1.0f / 127.0f);

        uint4 c0, c1;
        c0.x = packh2(v[0][0], v[0][1]);                   // base r,g
        c0.y = packh2(v[0][2], scale);                     // base b, scale
        c0.z = pack4b(q[1][0], q[2][0], q[3][0], q[4][0]); // dR c1..c4
        c0.w = pack4b(q[5][0], q[6][0], q[7][0], 0);       // dR c5..c7,0
        c1.x = pack4b(q[1][1], q[2][1], q[3][1], q[4][1]); // dG
        c1.y = pack4b(q[5][1], q[6][1], q[7][1], 0);
        c1.z = pack4b(q[1][2], q[2][2], q[3][2], q[4][2]); // dB
        c1.w = pack4b(q[5][2], q[6][2], q[7][2], 0);
        g_cells[2 * t]     = c0;
        g_cells[2 * t + 1] = c1;
    }
    if (t < 3 * 64) {
        int ch = t >> 6, i = t & 63;
        float v0 = lut1d[ch * 64 + min(i, 62)];
        float v1 = lut1d[ch * 64 + min(i, 62) + 1];
        g_pair1d[t] = __halves2half2(__float2half(v0), __float2half(v1));
    }
}

__device__ __forceinline__ float fma_rz(float a, float b, float c) {
    float d;
    asm("fma.rz.f32 %0, %1, %2, %3;" : "=f"(d) : "f"(a), "f"(b), "f"(c));
    return d;
}
__device__ __forceinline__ float fma_sat(float a, float b, float c) {
    float d;
    asm("fma.rn.sat.f32 %0, %1, %2, %3;" : "=f"(d) : "f"(a), "f"(b), "f"(c));
    return d;
}
__device__ __forceinline__ int dp2a_lo(unsigned a, unsigned b, int c) {
    int d;
    asm("dp2a.lo.s32.s32 %0, %1, %2, %3;" : "=r"(d) : "r"(a), "r"(b), "r"(c));
    return d;
}
__device__ __forceinline__ int dp2a_hi(unsigned a, unsigned b, int c) {
    int d;
    asm("dp2a.hi.s32.s32 %0, %1, %2, %3;" : "=r"(d) : "r"(a), "r"(b), "r"(c));
    return d;
}
__device__ __forceinline__ unsigned prmt_lo16(unsigned a, unsigned b) {
    unsigned d;
    asm("prmt.b32 %0, %1, %2, 0x5410;" : "=r"(d) : "r"(a), "r"(b));
    return d;
}

namespace {
constexpr float kMagic = 8388608.0f;   // 2^23: rz-fma puts floor() in mantissa
}

// 1D LUT + clip: x in [0,1) guaranteed -> no index clamps; SAT clip free.
__device__ __forceinline__ float apply1d(const __half2* __restrict__ s1,
                                         int ch, float v) {
    float fm = fma_rz(v, 63.0f, kMagic);
    float fl = fm - kMagic;                      // floor(v*63) as float
    float f  = fmaf(v, 63.0f, -fl);              // exact frac in [0,1]
    int   i  = (int)(__float_as_uint(fm) & 63u); // floor as int, <=62
    float2 p = __half22float2(s1[ch * 64 + i]);
    return fma_sat(f, p.y - p.x, p.x);           // clip to [0,1] for free
}

extern "C" __global__ void __launch_bounds__(kThreads, 1)
lut_main_kernel(const float* __restrict__ x, float* __restrict__ out,
                int ngrid)
{
    extern __shared__ char smem[];
    uint4*   sC = reinterpret_cast<uint4*>(smem);                 // 8192
    __half2* s1 = reinterpret_cast<__half2*>(smem + kCells * 32); // 192

    for (int i = threadIdx.x; i < 2 * kCells; i += kThreads) sC[i] = g_cells[i];
    for (int i = threadIdx.x; i < 3 * 64;     i += kThreads) s1[i] = g_pair1d[i];
    __syncthreads();

    const float kS3 = 15.9999990f;   // floor <= 15 under rz, no int clamp
    const int ngroups = kBatch * (kHW / 4);
    const int stride  = ngrid * kThreads;

    for (int gid = blockIdx.x * kThreads + threadIdx.x; gid < ngroups;
         gid += stride) {
        int img = gid >> 18;
        int q   = (gid & 0x3FFFF) << 2;
        const float* bin  = x   + (size_t)img * 3 * kHW + q;
        float*       bout = out + (size_t)img * 3 * kHW + q;

        float4 vr = *reinterpret_cast<const float4*>(bin);
        float4 vg = *reinterpret_cast<const float4*>(bin + kHW);
        float4 vb = *reinterpret_cast<const float4*>(bin + 2 * kHW);

        float ri[4] = {vr.x, vr.y, vr.z, vr.w};
        float gi[4] = {vg.x, vg.y, vg.z, vg.w};
        float bi[4] = {vb.x, vb.y, vb.z, vb.w};
        float ro[4], go[4], bo[4];

#pragma unroll
        for (int k = 0; k < 4; ++k) {
            // ---- 1D LUT + clip (SAT) ----
            float yr = apply1d(s1, 0, ri[k]);
            float yg = apply1d(s1, 1, gi[k]);
            float yb = apply1d(s1, 2, bi[k]);

            // ---- 3D index/frac via magic floor (no cvt, no clamps) ----
            float fmr = fma_rz(yr, kS3, kMagic);
            float fmg = fma_rz(yg, kS3, kMagic);
            float fmb = fma_rz(yb, kS3, kMagic);
            float fr  = fmaf(yr, kS3, -(fmr - kMagic));
            float fg  = fmaf(yg, kS3, -(fmg - kMagic));
            float fb  = fmaf(yb, kS3, -(fmb - kMagic));
            int ir = (int)(__float_as_uint(fmr) & 15u);
            int ig = (int)(__float_as_uint(fmg) & 15u);
            int ib = (int)(__float_as_uint(fmb) & 15u);

            // ---- weights (x16384), s16 via magic rounding ----
            float a0 = 1.0f - fr, g0 = 1.0f - fg;
            float b0s = (1.0f - fb) * 16384.0f, b1s = fb * 16384.0f;
            float t00 = g0 * b0s, t01 = g0 * b1s;
            float t10 = fg * b0s, t11 = fg * b1s;
            const float kRnd = 12582912.0f;  // 1.5*2^23
            unsigned m1 = __float_as_uint(fmaf(a0, t01, kRnd));
            unsigned m2 = __float_as_uint(fmaf(a0, t10, kRnd));
            unsigned m3 = __float_as_uint(fmaf(a0, t11, kRnd));
            unsigned m4 = __float_as_uint(fmaf(fr, t00, kRnd));
            unsigned m5 = __float_as_uint(fmaf(fr, t01, kRnd));
            unsigned m6 = __float_as_uint(fmaf(fr, t10, kRnd));
            unsigned m7 = __float_as_uint(fmaf(fr, t11, kRnd));
            unsigned wp0 = prmt_lo16(m1, m2);
            unsigned wp1 = prmt_lo16(m3, m4);
            unsigned wp2 = prmt_lo16(m5, m6);
            unsigned wp3 = m7 & 0xFFFF;

            // ---- one 32B interleaved cell: 2 x LDS.128 ----
            int c = (ir << 9) + (ig << 5) + (ib << 1);   // uint4 index = 2*cell
            uint4 u0 = sC[c];
            uint4 u1 = sC[c + 1];

            int aR = dp2a_lo(wp0, u0.z, 0);
            aR = dp2a_hi(wp1, u0.z, aR);
            aR = dp2a_lo(wp2, u0.w, aR);
            aR = dp2a_hi(wp3, u0.w, aR);
            int aG = dp2a_lo(wp0, u1.x, 0);
            aG = dp2a_hi(wp1, u1.x, aG);
            aG = dp2a_lo(wp2, u1.y, aG);
            aG = dp2a_hi(wp3, u1.y, aG);
            int aB = dp2a_lo(wp0, u1.z, 0);
            aB = dp2a_hi(wp1, u1.z, aB);
            aB = dp2a_lo(wp2, u1.w, aB);
            aB = dp2a_hi(wp3, u1.w, aB);

            float2 brg = __half22float2(*reinterpret_cast<__half2*>(&u0.x));
            float2 bbs = __half22float2(*reinterpret_cast<__half2*>(&u0.y));
            float fs = bbs.y * (1.0f / 16384.0f);

            ro[k] = fmaf((float)aR, fs, brg.x);
            go[k] = fmaf((float)aG, fs, brg.y);
            bo[k] = fmaf((float)aB, fs, bbs.x);
        }

        *reinterpret_cast<float4*>(bout)           = make_float4(ro[0], ro[1], ro[2], ro[3]);
        *reinterpret_cast<float4*>(bout + kHW)     = make_float4(go[0], go[1], go[2], go[3]);
        *reinterpret_cast<float4*>(bout + 2 * kHW) = make_float4(bo[0], bo[1], bo[2], bo[3]);
    }
}

extern "C" void kernel_launch(void* const* d_in, const int* in_sizes, int n_in,
                              void* d_out, int out_size) {
    (void)in_sizes; (void)n_in; (void)out_size;
    const float* x     = (const float*)d_in[0];
    const float* lut1d = (const float*)d_in[1];
    const float* lut3d = (const float*)d_in[2];
    float* out = (float*)d_out;

    static int nsm = 0;
    if (nsm == 0) {
        cudaDeviceProp prop;
        cudaGetDeviceProperties(&prop, 0);
        nsm = prop.multiProcessorCount;
        cudaFuncSetAttribute(lut_main_kernel,
                             cudaFuncAttributeMaxDynamicSharedMemorySize,
                             kSmemBytes);
    }

    lut_prep_kernel<<<(kCells + 255) / 256, 256>>>(lut1d, lut3d);
    lut_main_kernel<<<nsm, kThreads, kSmemBytes>>>(x, out, nsm);
}

// round 8
// speedup vs baseline: 1.0667x; 1.0667x over previous
#include <cuda_runtime.h>
#include <cuda_fp16.h>

// Fused LUT color-grade, GB300 (sm_103a), round 8.
// x: (4,3,1024,1024) f32, lut1d: (3,64) f32, lut3d: (17,17,17,3) f32.
//
// R7 post-mortem: interleaved 32B cell records collapsed LDS.128 bank
// coverage from 8 groups to 4 -> conflicts up, net regression. This round
// keeps R7's instruction diet (magic floor/frac, fma.sat clip, dp2a sums)
// but restores R6's SPLIT cell arrays (16B stride each, full bank spread).
//   cell chunk0 (sC0): base c000 (3 fp16) + scale (fp16) + 7 int8 R-deltas
//   cell chunk1 (sC1): 7 int8 G-deltas + pad + 7 int8 B-deltas + pad

namespace {
constexpr int kHW      = 1024 * 1024;
constexpr int kBatch   = 4;
constexpr int kM       = 17;
constexpr int kCells   = 16 * 16 * 16;               // 4096
constexpr int kThreads = 1024;
constexpr int kSmemBytes = kCells * 32 + 3 * 64 * 4; // 131,840 B
}  // namespace

__device__ uint4   g_c0[kCells];
__device__ uint4   g_c1[kCells];
__device__ __half2 g_pair1d[3 * 64];

static __device__ __forceinline__ unsigned packh2(float a, float b) {
    __half2 h = __halves2half2(__float2half(a), __float2half(b));
    return *reinterpret_cast<unsigned*>(&h);
}
static __device__ __forceinline__ unsigned pack4b(int b0, int b1, int b2, int b3) {
    return (unsigned)(b0 & 0xFF) | ((unsigned)(b1 & 0xFF) << 8) |
           ((unsigned)(b2 & 0xFF) << 16) | ((unsigned)(b3 & 0xFF) << 24);
}

extern "C" __global__ void lut_prep_kernel(const float* __restrict__ lut1d,
                                           const float* __restrict__ lut3d) {
    int t = blockIdx.x * blockDim.x + threadIdx.x;
    if (t < kCells) {
        int ir = t >> 8, ig = (t >> 4) & 15, ib = t & 15;
        float v[8][3];
#pragma unroll
        for (int c = 0; c < 8; ++c) {
            int dr = c >> 2, dg = (c >> 1) & 1, db = c & 1;
            const float* p =
                lut3d + (((ir + dr) * kM + (ig + dg)) * kM + (ib + db)) * 3;
            v[c][0] = p[0]; v[c][1] = p[1]; v[c][2] = p[2];
        }
        float d[8][3];
        float maxd = 0.0f;
#pragma unroll
        for (int c = 1; c < 8; ++c)
#pragma unroll
            for (int ch = 0; ch < 3; ++ch) {
                d[c][ch] = v[c][ch] - v[0][ch];
                maxd = fmaxf(maxd, fabsf(d[c][ch]));
            }
        float inv = (maxd > 0.0f) ? 127.0f / maxd : 0.0f;
        int q[8][3];
#pragma unroll
        for (int c = 1; c < 8; ++c)
#pragma unroll
            for (int ch = 0; ch < 3; ++ch) {
                int qq = __float2int_rn(d[c][ch] * inv);
                q[c][ch] = max(-127, min(127, qq));
            }
        float scale = maxd * (1.0f / 127.0f);

        uint4 c0, c1;
        c0.x = packh2(v[0][0], v[0][1]);                   // base r,g
        c0.y = packh2(v[0][2], scale);                     // base b, scale
        c0.z = pack4b(q[1][0], q[2][0], q[3][0], q[4][0]); // dR c1..c4
        c0.w = pack4b(q[5][0], q[6][0], q[7][0], 0);       // dR c5..c7,0
        c1.x = pack4b(q[1][1], q[2][1], q[3][1], q[4][1]); // dG
        c1.y = pack4b(q[5][1], q[6][1], q[7][1], 0);
        c1.z = pack4b(q[1][2], q[2][2], q[3][2], q[4][2]); // dB
        c1.w = pack4b(q[5][2], q[6][2], q[7][2], 0);
        g_c0[t] = c0;
        g_c1[t] = c1;
    }
    if (t < 3 * 64) {
        int ch = t >> 6, i = t & 63;
        float v0 = lut1d[ch * 64 + min(i, 62)];
        float v1 = lut1d[ch * 64 + min(i, 62) + 1];
        g_pair1d[t] = __halves2half2(__float2half(v0), __float2half(v1));
    }
}

__device__ __forceinline__ float fma_rz(float a, float b, float c) {
    float d;
    asm("fma.rz.f32 %0, %1, %2, %3;" : "=f"(d) : "f"(a), "f"(b), "f"(c));
    return d;
}
__device__ __forceinline__ float fma_sat(float a, float b, float c) {
    float d;
    asm("fma.rn.sat.f32 %0, %1, %2, %3;" : "=f"(d) : "f"(a), "f"(b), "f"(c));
    return d;
}
__device__ __forceinline__ int dp2a_lo(unsigned a, unsigned b, int c) {
    int d;
    asm("dp2a.lo.s32.s32 %0, %1, %2, %3;" : "=r"(d) : "r"(a), "r"(b), "r"(c));
    return d;
}
__device__ __forceinline__ int dp2a_hi(unsigned a, unsigned b, int c) {
    int d;
    asm("dp2a.hi.s32.s32 %0, %1, %2, %3;" : "=r"(d) : "r"(a), "r"(b), "r"(c));
    return d;
}
__device__ __forceinline__ unsigned prmt_lo16(unsigned a, unsigned b) {
    unsigned d;
    asm("prmt.b32 %0, %1, %2, 0x5410;" : "=r"(d) : "r"(a), "r"(b));
    return d;
}

namespace {
constexpr float kMagic = 8388608.0f;   // 2^23: rz-fma puts floor() in mantissa
}

// 1D LUT + clip: x in [0,1) -> no index clamps; SAT clip free.
__device__ __forceinline__ float apply1d(const __half2* __restrict__ s1,
                                         int ch, float v) {
    float fm = fma_rz(v, 63.0f, kMagic);
    float fl = fm - kMagic;                      // floor(v*63) as float
    float f  = fmaf(v, 63.0f, -fl);              // exact frac in [0,1]
    int   i  = (int)(__float_as_uint(fm) & 63u); // floor as int, <=62
    float2 p = __half22float2(s1[ch * 64 + i]);
    return fma_sat(f, p.y - p.x, p.x);           // clip to [0,1] for free
}

extern "C" __global__ void __launch_bounds__(kThreads, 1)
lut_main_kernel(const float* __restrict__ x, float* __restrict__ out,
                int ngrid)
{
    extern __shared__ char smem[];
    uint4*   sC0 = reinterpret_cast<uint4*>(smem);                  // 4096
    uint4*   sC1 = reinterpret_cast<uint4*>(smem + kCells * 16);    // 4096
    __half2* s1  = reinterpret_cast<__half2*>(smem + kCells * 32);  // 192

    for (int i = threadIdx.x; i < kCells; i += kThreads) sC0[i] = g_c0[i];
    for (int i = threadIdx.x; i < kCells; i += kThreads) sC1[i] = g_c1[i];
    for (int i = threadIdx.x; i < 3 * 64; i += kThreads) s1[i]  = g_pair1d[i];
    __syncthreads();

    const float kS3 = 15.9999990f;   // floor <= 15 under rz, no int clamp
    const int ngroups = kBatch * (kHW / 4);
    const int stride  = ngrid * kThreads;

    for (int gid = blockIdx.x * kThreads + threadIdx.x; gid < ngroups;
         gid += stride) {
        int img = gid >> 18;
        int q   = (gid & 0x3FFFF) << 2;
        const float* bin  = x   + (size_t)img * 3 * kHW + q;
        float*       bout = out + (size_t)img * 3 * kHW + q;

        float4 vr = *reinterpret_cast<const float4*>(bin);
        float4 vg = *reinterpret_cast<const float4*>(bin + kHW);
        float4 vb = *reinterpret_cast<const float4*>(bin + 2 * kHW);

        float ri[4] = {vr.x, vr.y, vr.z, vr.w};
        float gi[4] = {vg.x, vg.y, vg.z, vg.w};
        float bi[4] = {vb.x, vb.y, vb.z, vb.w};
        float ro[4], go[4], bo[4];

#pragma unroll
        for (int k = 0; k < 4; ++k) {
            // ---- 1D LUT + clip (SAT) ----
            float yr = apply1d(s1, 0, ri[k]);
            float yg = apply1d(s1, 1, gi[k]);
            float yb = apply1d(s1, 2, bi[k]);

            // ---- 3D index/frac via magic floor (no cvt, no clamps) ----
            float fmr = fma_rz(yr, kS3, kMagic);
            float fmg = fma_rz(yg, kS3, kMagic);
            float fmb = fma_rz(yb, kS3, kMagic);
            float fr  = fmaf(yr, kS3, -(fmr - kMagic));
            float fg  = fmaf(yg, kS3, -(fmg - kMagic));
            float fb  = fmaf(yb, kS3, -(fmb - kMagic));
            int ir = (int)(__float_as_uint(fmr) & 15u);
            int ig = (int)(__float_as_uint(fmg) & 15u);
            int ib = (int)(__float_as_uint(fmb) & 15u);

            // ---- weights (x16384), s16 via magic rounding ----
            float a0 = 1.0f - fr, g0 = 1.0f - fg;
            float b0s = (1.0f - fb) * 16384.0f, b1s = fb * 16384.0f;
            float t00 = g0 * b0s, t01 = g0 * b1s;
            float t10 = fg * b0s, t11 = fg * b1s;
            const float kRnd = 12582912.0f;  // 1.5*2^23
            unsigned m1 = __float_as_uint(fmaf(a0, t01, kRnd));
            unsigned m2 = __float_as_uint(fmaf(a0, t10, kRnd));
            unsigned m3 = __float_as_uint(fmaf(a0, t11, kRnd));
            unsigned m4 = __float_as_uint(fmaf(fr, t00, kRnd));
            unsigned m5 = __float_as_uint(fmaf(fr, t01, kRnd));
            unsigned m6 = __float_as_uint(fmaf(fr, t10, kRnd));
            unsigned m7 = __float_as_uint(fmaf(fr, t11, kRnd));
            unsigned wp0 = prmt_lo16(m1, m2);
            unsigned wp1 = prmt_lo16(m3, m4);
            unsigned wp2 = prmt_lo16(m5, m6);
            unsigned wp3 = m7 & 0xFFFF;

            // ---- one 32B cell: 2 x LDS.128 from SPLIT arrays ----
            int c = (ir << 8) + (ig << 4) + ib;
            uint4 u0 = sC0[c];
            uint4 u1 = sC1[c];

            int aR = dp2a_lo(wp0, u0.z, 0);
            aR = dp2a_hi(wp1, u0.z, aR);
            aR = dp2a_lo(wp2, u0.w, aR);
            aR = dp2a_hi(wp3, u0.w, aR);
            int aG = dp2a_lo(wp0, u1.x, 0);
            aG = dp2a_hi(wp1, u1.x, aG);
            aG = dp2a_lo(wp2, u1.y, aG);
            aG = dp2a_hi(wp3, u1.y, aG);
            int aB = dp2a_lo(wp0, u1.z, 0);
            aB = dp2a_hi(wp1, u1.z, aB);
            aB = dp2a_lo(wp2, u1.w, aB);
            aB = dp2a_hi(wp3, u1.w, aB);

            float2 brg = __half22float2(*reinterpret_cast<__half2*>(&u0.x));
            float2 bbs = __half22float2(*reinterpret_cast<__half2*>(&u0.y));
            float fs = bbs.y * (1.0f / 16384.0f);

            ro[k] = fmaf((float)aR, fs, brg.x);
            go[k] = fmaf((float)aG, fs, brg.y);
            bo[k] = fmaf((float)aB, fs, bbs.x);
        }

        *reinterpret_cast<float4*>(bout)           = make_float4(ro[0], ro[1], ro[2], ro[3]);
        *reinterpret_cast<float4*>(bout + kHW)     = make_float4(go[0], go[1], go[2], go[3]);
        *reinterpret_cast<float4*>(bout + 2 * kHW) = make_float4(bo[0], bo[1], bo[2], bo[3]);
    }
}

extern "C" void kernel_launch(void* const* d_in, const int* in_sizes, int n_in,
                              void* d_out, int out_size) {
    (void)in_sizes; (void)n_in; (void)out_size;
    const float* x     = (const float*)d_in[0];
    const float* lut1d = (const float*)d_in[1];
    const float* lut3d = (const float*)d_in[2];
    float* out = (float*)d_out;

    static int nsm = 0;
    if (nsm == 0) {
        cudaDeviceProp prop;
        cudaGetDeviceProperties(&prop, 0);
        nsm = prop.multiProcessorCount;
        cudaFuncSetAttribute(lut_main_kernel,
                             cudaFuncAttributeMaxDynamicSharedMemorySize,
                             kSmemBytes);
    }

    lut_prep_kernel<<<(kCells + 255) / 256, 256>>>(lut1d, lut3d);
    lut_main_kernel<<<nsm, kThreads, kSmemBytes>>>(x, out, nsm);
}

// round 10
// speedup vs baseline: 1.0935x; 1.0252x over previous
#include <cuda_runtime.h>
#include <cuda_fp16.h>

// Fused LUT color-grade, GB300 (sm_103a), round 10 (= R9 resubmit; R9 hit an
// infra flake, never ran).
// x: (4,3,1024,1024) f32, lut1d: (3,64) f32, lut3d: (17,17,17,3) f32.
//
// R8 L1 budget (142 cyc/warp-iter, model == measurement):
//   cells 77 | 1D-LUT conflicts 41 | global 24.
// This round: replicate the 1D pair-table 32x (one copy per smem bank,
// lane L reads bank L) -> 1D term 41 -> 12 cyc, conflict-free.
//   cell chunk0 (sC0): base c000 (3 fp16) + scale (fp16) + 7 int8 R-deltas
//   cell chunk1 (sC1): 7 int8 G-deltas + pad + 7 int8 B-deltas + pad
//   res_ch = base_ch + (sum w_c * d_c) * scale/16384 via dp2a on s16 weights.

namespace {
constexpr int kHW      = 1024 * 1024;
constexpr int kBatch   = 4;
constexpr int kM       = 17;
constexpr int kCells   = 16 * 16 * 16;               // 4096
constexpr int kThreads = 1024;
constexpr int kRep1    = 3 * 64 * 32;                // replicated 1D entries
// smem: sC0 (64K) + sC1 (64K) + replicated 1D (24K)
constexpr int kSmemBytes = kCells * 32 + kRep1 * 4;  // 155,648 B
}  // namespace

__device__ uint4   g_c0[kCells];
__device__ uint4   g_c1[kCells];
__device__ __half2 g_pair1d[3 * 64];

static __device__ __forceinline__ unsigned packh2(float a, float b) {
    __half2 h = __halves2half2(__float2half(a), __float2half(b));
    return *reinterpret_cast<unsigned*>(&h);
}
static __device__ __forceinline__ unsigned pack4b(int b0, int b1, int b2, int b3) {
    return (unsigned)(b0 & 0xFF) | ((unsigned)(b1 & 0xFF) << 8) |
           ((unsigned)(b2 & 0xFF) << 16) | ((unsigned)(b3 & 0xFF) << 24);
}

extern "C" __global__ void lut_prep_kernel(const float* __restrict__ lut1d,
                                           const float* __restrict__ lut3d) {
    int t = blockIdx.x * blockDim.x + threadIdx.x;
    if (t < kCells) {
        int ir = t >> 8, ig = (t >> 4) & 15, ib = t & 15;
        float v[8][3];
#pragma unroll
        for (int c = 0; c < 8; ++c) {
            int dr = c >> 2, dg = (c >> 1) & 1, db = c & 1;
            const float* p =
                lut3d + (((ir + dr) * kM + (ig + dg)) * kM + (ib + db)) * 3;
            v[c][0] = p[0]; v[c][1] = p[1]; v[c][2] = p[2];
        }
        float d[8][3];
        float maxd = 0.0f;
#pragma unroll
        for (int c = 1; c < 8; ++c)
#pragma unroll
            for (int ch = 0; ch < 3; ++ch) {
                d[c][ch] = v[c][ch] - v[0][ch];
                maxd = fmaxf(maxd, fabsf(d[c][ch]));
            }
        float inv = (maxd > 0.0f) ? 127.0f / maxd : 0.0f;
        int q[8][3];
#pragma unroll
        for (int c = 1; c < 8; ++c)
#pragma unroll
            for (int ch = 0; ch < 3; ++ch) {
                int qq = __float2int_rn(d[c][ch] * inv);
                q[c][ch] = max(-127, min(127, qq));
            }
        float scale = maxd * (1.0f / 127.0f);

        uint4 c0, c1;
        c0.x = packh2(v[0][0], v[0][1]);                   // base r,g
        c0.y = packh2(v[0][2], scale);                     // base b, scale
        c0.z = pack4b(q[1][0], q[2][0], q[3][0], q[4][0]); // dR c1..c4
        c0.w = pack4b(q[5][0], q[6][0], q[7][0], 0);       // dR c5..c7,0
        c1.x = pack4b(q[1][1], q[2][1], q[3][1], q[4][1]); // dG
        c1.y = pack4b(q[5][1], q[6][1], q[7][1], 0);
        c1.z = pack4b(q[1][2], q[2][2], q[3][2], q[4][2]); // dB
        c1.w = pack4b(q[5][2], q[6][2], q[7][2], 0);
        g_c0[t] = c0;
        g_c1[t] = c1;
    }
    if (t < 3 * 64) {
        int ch = t >> 6, i = t & 63;
        float v0 = lut1d[ch * 64 + min(i, 62)];
        float v1 = lut1d[ch * 64 + min(i, 62) + 1];
        g_pair1d[t] = __halves2half2(__float2half(v0), __float2half(v1));
    }
}

__device__ __forceinline__ float fma_rz(float a, float b, float c) {
    float d;
    asm("fma.rz.f32 %0, %1, %2, %3;" : "=f"(d) : "f"(a), "f"(b), "f"(c));
    return d;
}
__device__ __forceinline__ float fma_sat(float a, float b, float c) {
    float d;
    asm("fma.rn.sat.f32 %0, %1, %2, %3;" : "=f"(d) : "f"(a), "f"(b), "f"(c));
    return d;
}
__device__ __forceinline__ int dp2a_lo(unsigned a, unsigned b, int c) {
    int d;
    asm("dp2a.lo.s32.s32 %0, %1, %2, %3;" : "=r"(d) : "r"(a), "r"(b), "r"(c));
    return d;
}
__device__ __forceinline__ int dp2a_hi(unsigned a, unsigned b, int c) {
    int d;
    asm("dp2a.hi.s32.s32 %0, %1, %2, %3;" : "=r"(d) : "r"(a), "r"(b), "r"(c));
    return d;
}
__device__ __forceinline__ unsigned prmt_lo16(unsigned a, unsigned b) {
    unsigned d;
    asm("prmt.b32 %0, %1, %2, 0x5410;" : "=r"(d) : "r"(a), "r"(b));
    return d;
}

namespace {
constexpr float kMagic = 8388608.0f;   // 2^23: rz-fma puts floor() in mantissa
}

// Replicated 1D lookup: table entry (ch,i), copy `lane`, at index
// ((ch*64 + i) << 5) + lane -> bank == lane, always conflict-free.
__device__ __forceinline__ float apply1d_rep(const __half2* __restrict__ s1,
                                             int chbase, float v) {
    float fm = fma_rz(v, 63.0f, kMagic);
    float fl = fm - kMagic;                      // floor(v*63) as float
    float f  = fmaf(v, 63.0f, -fl);              // exact frac in [0,1]
    int   i  = (int)(__float_as_uint(fm) & 63u); // floor as int, <=62
    float2 p = __half22float2(s1[chbase + (i << 5)]);
    return fma_sat(f, p.y - p.x, p.x);           // clip to [0,1] free
}

extern "C" __global__ void __launch_bounds__(kThreads, 1)
lut_main_kernel(const float* __restrict__ x, float* __restrict__ out,
                int ngrid)
{
    extern __shared__ char smem[];
    uint4*   sC0 = reinterpret_cast<uint4*>(smem);                  // 4096
    uint4*   sC1 = reinterpret_cast<uint4*>(smem + kCells * 16);    // 4096
    __half2* s1  = reinterpret_cast<__half2*>(smem + kCells * 32);  // 6144

    for (int i = threadIdx.x; i < kCells; i += kThreads) sC0[i] = g_c0[i];
    for (int i = threadIdx.x; i < kCells; i += kThreads) sC1[i] = g_c1[i];
    // fill replicated 1D: entry e = i>>5 broadcast to 32 bank copies
    for (int i = threadIdx.x; i < kRep1; i += kThreads) s1[i] = g_pair1d[i >> 5];
    __syncthreads();

    const int lane = threadIdx.x & 31;
    const int cb0 = lane;            // ch 0 base
    const int cb1 = lane + 2048;     // ch 1 base (64<<5)
    const int cb2 = lane + 4096;     // ch 2 base

    const float kS3 = 15.9999990f;   // floor <= 15 under rz, no int clamp
    const int ngroups = kBatch * (kHW / 4);
    const int stride  = ngrid * kThreads;

    for (int gid = blockIdx.x * kThreads + threadIdx.x; gid < ngroups;
         gid += stride) {
        int img = gid >> 18;
        int q   = (gid & 0x3FFFF) << 2;
        const float* bin  = x   + (size_t)img * 3 * kHW + q;
        float*       bout = out + (size_t)img * 3 * kHW + q;

        float4 vr = *reinterpret_cast<const float4*>(bin);
        float4 vg = *reinterpret_cast<const float4*>(bin + kHW);
        float4 vb = *reinterpret_cast<const float4*>(bin + 2 * kHW);

        float ri[4] = {vr.x, vr.y, vr.z, vr.w};
        float gi[4] = {vg.x, vg.y, vg.z, vg.w};
        float bi[4] = {vb.x, vb.y, vb.z, vb.w};
        float ro[4], go[4], bo[4];

#pragma unroll
        for (int k = 0; k < 4; ++k) {
            // ---- 1D LUT + clip (conflict-free replicated table) ----
            float yr = apply1d_rep(s1, cb0, ri[k]);
            float yg = apply1d_rep(s1, cb1, gi[k]);
            float yb = apply1d_rep(s1, cb2, bi[k]);

            // ---- 3D index/frac via magic floor (no cvt, no clamps) ----
            float fmr = fma_rz(yr, kS3, kMagic);
            float fmg = fma_rz(yg, kS3, kMagic);
            float fmb = fma_rz(yb, kS3, kMagic);
            float fr  = fmaf(yr, kS3, -(fmr - kMagic));
            float fg  = fmaf(yg, kS3, -(fmg - kMagic));
            float fb  = fmaf(yb, kS3, -(fmb - kMagic));
            int ir = (int)(__float_as_uint(fmr) & 15u);
            int ig = (int)(__float_as_uint(fmg) & 15u);
            int ib = (int)(__float_as_uint(fmb) & 15u);

            // ---- weights (x16384), s16 via magic rounding ----
            float a0 = 1.0f - fr, g0 = 1.0f - fg;
            float b0s = (1.0f - fb) * 16384.0f, b1s = fb * 16384.0f;
            float t00 = g0 * b0s, t01 = g0 * b1s;
            float t10 = fg * b0s, t11 = fg * b1s;
            const float kRnd = 12582912.0f;  // 1.5*2^23
            unsigned m1 = __float_as_uint(fmaf(a0, t01, kRnd));
            unsigned m2 = __float_as_uint(fmaf(a0, t10, kRnd));
            unsigned m3 = __float_as_uint(fmaf(a0, t11, kRnd));
            unsigned m4 = __float_as_uint(fmaf(fr, t00, kRnd));
            unsigned m5 = __float_as_uint(fmaf(fr, t01, kRnd));
            unsigned m6 = __float_as_uint(fmaf(fr, t10, kRnd));
            unsigned m7 = __float_as_uint(fmaf(fr, t11, kRnd));
            unsigned wp0 = prmt_lo16(m1, m2);
            unsigned wp1 = prmt_lo16(m3, m4);
            unsigned wp2 = prmt_lo16(m5, m6);
            unsigned wp3 = m7 & 0xFFFF;

            // ---- one 32B cell: 2 x LDS.128 from split arrays ----
            int c = (ir << 8) + (ig << 4) + ib;
            uint4 u0 = sC0[c];
            uint4 u1 = sC1[c];

            int aR = dp2a_lo(wp0, u0.z, 0);
            aR = dp2a_hi(wp1, u0.z, aR);
            aR = dp2a_lo(wp2, u0.w, aR);
            aR = dp2a_hi(wp3, u0.w, aR);
            int aG = dp2a_lo(wp0, u1.x, 0);
            aG = dp2a_hi(wp1, u1.x, aG);
            aG = dp2a_lo(wp2, u1.y, aG);
            aG = dp2a_hi(wp3, u1.y, aG);
            int aB = dp2a_lo(wp0, u1.z, 0);
            aB = dp2a_hi(wp1, u1.z, aB);
            aB = dp2a_lo(wp2, u1.w, aB);
            aB = dp2a_hi(wp3, u1.w, aB);

            float2 brg = __half22float2(*reinterpret_cast<__half2*>(&u0.x));
            float2 bbs = __half22float2(*reinterpret_cast<__half2*>(&u0.y));
            float fs = bbs.y * (1.0f / 16384.0f);

            ro[k] = fmaf((float)aR, fs, brg.x);
            go[k] = fmaf((float)aG, fs, brg.y);
            bo[k] = fmaf((float)aB, fs, bbs.x);
        }

        *reinterpret_cast<float4*>(bout)           = make_float4(ro[0], ro[1], ro[2], ro[3]);
        *reinterpret_cast<float4*>(bout + kHW)     = make_float4(go[0], go[1], go[2], go[3]);
        *reinterpret_cast<float4*>(bout + 2 * kHW) = make_float4(bo[0], bo[1], bo[2], bo[3]);
    }
}

extern "C" void kernel_launch(void* const* d_in, const int* in_sizes, int n_in,
                              void* d_out, int out_size) {
    (void)in_sizes; (void)n_in; (void)out_size;
    const float* x     = (const float*)d_in[0];
    const float* lut1d = (const float*)d_in[1];
    const float* lut3d = (const float*)d_in[2];
    float* out = (float*)d_out;

    static int nsm = 0;
    if (nsm == 0) {
        cudaDeviceProp prop;
        cudaGetDeviceProperties(&prop, 0);
        nsm = prop.multiProcessorCount;
        cudaFuncSetAttribute(lut_main_kernel,
                             cudaFuncAttributeMaxDynamicSharedMemorySize,
                             kSmemBytes);
    }

    lut_prep_kernel<<<(kCells + 255) / 256, 256>>>(lut1d, lut3d);
    lut_main_kernel<<<nsm, kThreads, kSmemBytes>>>(x, out, nsm);
}